// round 2
// baseline (speedup 1.0000x reference)
#include <cuda_runtime.h>

#define K_OBJ 256
#define TILE  256

// ---- scratch (no allocations allowed; __device__ globals) ----
__device__ unsigned long long g_key[K_OBJ];
__device__ int   g_counts[K_OBJ];
__device__ float g_xk_x[K_OBJ], g_xk_y[K_OBJ], g_qa[K_OBJ], g_ba[K_OBJ];
__device__ float g_att[K_OBJ], g_rep[K_OBJ], g_corr[K_OBJ], g_den[K_OBJ], g_num[K_OBJ];
__device__ float g_noise_sum;
__device__ int   g_noise_cnt;

__device__ __forceinline__ float clip_beta(float b) {
    return fminf(fmaxf(b, 0.0f), 0.99999f); // BETA_CLIP = 1 - 1e-5
}

// ---- K1: zero scratch (re-run every launch: graph-replay determinism) ----
__global__ void k_init() {
    int k = threadIdx.x;
    g_key[k] = 0ull;
    g_counts[k] = 0;
    g_att[k] = 0.f; g_rep[k] = 0.f; g_corr[k] = 0.f; g_den[k] = 0.f; g_num[k] = 0.f;
    if (k == 0) { g_noise_sum = 0.f; g_noise_cnt = 0; }
}

// ---- K2: counts + argmax-beta per object (lowest-index tie-break) ----
__global__ void k_pass1(const float* __restrict__ pred_beta,
                        const int*   __restrict__ t_idx, int n) {
    int i = blockIdx.x * blockDim.x + threadIdx.x;
    if (i >= n) return;
    int t = t_idx[i];
    if (t >= 0) {
        float b = clip_beta(pred_beta[i]);
        // beta >= 0 -> float bits monotone as uint. High bits = beta, low = ~i
        // so atomicMax picks max beta, then lowest index on ties (JAX argmax).
        unsigned long long key =
            ((unsigned long long)__float_as_uint(b) << 32) |
            (unsigned long long)(~(unsigned int)i);
        atomicMax(&g_key[t], key);
        atomicAdd(&g_counts[t], 1);
    }
}

// ---- K3: gather alpha-point properties ----
__global__ void k_gather(const float* __restrict__ pred_beta,
                         const float* __restrict__ cc) {
    int k = threadIdx.x;
    unsigned int idx = ~(unsigned int)(g_key[k] & 0xFFFFFFFFull);
    if (g_counts[k] == 0) idx = 0u;   // invalid object: value irrelevant (masked)
    float b = clip_beta(pred_beta[idx]);
    float a = atanhf(b);
    g_qa[k]   = a * a + 0.5f;         // Q_MIN = 0.5
    g_ba[k]   = b;
    g_xk_x[k] = cc[2u * idx];
    g_xk_y[k] = cc[2u * idx + 1u];
}

// ---- K4a: per-point scatter: attraction, payload, member-hinge corr, noise ----
__global__ void k_point(const float* __restrict__ pred_beta,
                        const float* __restrict__ cc,
                        const float* __restrict__ pred_energy,
                        const float* __restrict__ pred_pos,
                        const float* __restrict__ pred_time,
                        const float* __restrict__ pred_id,
                        const float* __restrict__ t_energy,
                        const float* __restrict__ t_pos,
                        const float* __restrict__ t_time,
                        const int*   __restrict__ t_idx, int n) {
    int i = blockIdx.x * blockDim.x + threadIdx.x;
    if (i >= n) return;
    float braw = pred_beta[i];
    float b = clip_beta(braw);
    int t = t_idx[i];
    if (t < 0) {
        atomicAdd(&g_noise_sum, b);   // S_B = 1.0
        atomicAdd(&g_noise_cnt, 1);
        return;
    }
    float a = atanhf(b);
    float q = a * a + 0.5f;
    float dx = cc[2 * i]     - g_xk_x[t];
    float dy = cc[2 * i + 1] - g_xk_y[t];
    float d2 = dx * dx + dy * dy;
    atomicAdd(&g_att[t], q * d2);                 // attraction numerator (x q_alpha later)
    float h = 1.0f - sqrtf(d2 + 1e-6f);
    if (h > 0.0f) atomicAdd(&g_corr[t], q * h);   // remove own-member term from rep_full
    // payload: pw = beta * not_noise ; den counts ALL members' pw
    atomicAdd(&g_den[t], b);
    if (braw >= 0.1f) {                            // PAYLOAD_BETA_CLIP
        float te = t_energy[i];
        float ew = (te > 10.0f) ? 1.0f : fmaxf((te - 0.5f) / 9.5f, 0.0f);
        float de = te - pred_energy[i];
        float e_loss = de * de / (te + 1.0f);      // ENERGY_DEN_OFFSET=1, den>0 always
        float p0 = t_pos[2 * i]     - pred_pos[2 * i];
        float p1 = t_pos[2 * i + 1] - pred_pos[2 * i + 1];
        float p_loss = (p0 * p0 + p1 * p1) * 0.01f;
        float dt = t_time[i] - pred_time[i];
        float tm_loss = dt * dt;
        float s = 0.0f;
        #pragma unroll
        for (int c = 0; c < 6; c++) { float v = pred_id[6 * i + c]; s += v * v; }
        float cls_loss = 1e-8f * (s * (1.0f / 6.0f));
        float pay = (e_loss + p_loss + tm_loss + cls_loss) * ew;
        atomicAdd(&g_num[t], pay * b);
    }
}

// ---- K4b: hot loop. thread = object k (x_k in regs), tile of points in smem ----
__global__ void __launch_bounds__(256) k_rep(const float* __restrict__ pred_beta,
                                             const float* __restrict__ cc, int n) {
    __shared__ float4 s_pt[TILE];   // (ccx, ccy, q, unused)
    int tid = threadIdx.x;
    float kx = g_xk_x[tid], ky = g_xk_y[tid];
    float rep = 0.0f;
    int base = blockIdx.x * TILE;
    int cnt = n - base; if (cnt > TILE) cnt = TILE;
    for (int p = tid; p < cnt; p += 256) {
        int i = base + p;
        float b = clip_beta(pred_beta[i]);
        float a = atanhf(b);
        s_pt[p] = make_float4(cc[2 * i], cc[2 * i + 1], a * a + 0.5f, 0.0f);
    }
    __syncthreads();
    #pragma unroll 4
    for (int p = 0; p < cnt; p++) {
        float4 P = s_pt[p];                    // broadcast LDS.128
        float dx = P.x - kx, dy = P.y - ky;
        float d2 = dx * dx + dy * dy;
        if (d2 < 0.999999f) {                  // hinge>0 <=> d2 < 1-1e-6; skip 78% of MUFU
            float h = 1.0f - sqrtf(d2 + 1e-6f);
            rep += P.z * h;
        }
    }
    atomicAdd(&g_rep[tid], rep);               // one REDG per thread per block
}

// ---- K5: final reduce -> scalar ----
__global__ void k_final(float* __restrict__ out, int n) {
    __shared__ double s_sum[K_OBJ];
    __shared__ int    s_nv[K_OBJ];
    int k = threadIdx.x;
    int c = g_counts[k];
    double term = 0.0; int nv = 0;
    if (c > 0) {
        double qa = (double)g_qa[k];
        term += qa * (double)g_att[k] / (double)c;                 // V_att_k
        int dr = n - c; if (dr < 1) dr = 1;
        term += qa * (double)(g_rep[k] - g_corr[k]) / (double)dr;  // V_rep_k
        term += 1.0 - (double)g_ba[k];                             // L_beta_k
        float den = fmaxf(g_den[k], 1e-6f);
        term += (double)g_num[k] / (double)den;                    // payload_k
        nv = 1;
    }
    s_sum[k] = term; s_nv[k] = nv;
    __syncthreads();
    #pragma unroll
    for (int s = 128; s > 0; s >>= 1) {
        if (k < s) { s_sum[k] += s_sum[k + s]; s_nv[k] += s_nv[k + s]; }
        __syncthreads();
    }
    if (k == 0) {
        double nvd = (s_nv[0] > 0) ? (double)s_nv[0] : 1.0;
        int nc = (g_noise_cnt > 0) ? g_noise_cnt : 1;
        double res = s_sum[0] / nvd + (double)g_noise_sum / (double)nc;
        out[0] = (float)res;
    }
}

extern "C" void kernel_launch(void* const* d_in, const int* in_sizes, int n_in,
                              void* d_out, int out_size) {
    const float* pred_beta    = (const float*)d_in[0];
    const float* pred_ccoords = (const float*)d_in[1];
    const float* pred_energy  = (const float*)d_in[2];
    const float* pred_pos     = (const float*)d_in[3];
    const float* pred_time    = (const float*)d_in[4];
    const float* pred_id      = (const float*)d_in[5];
    const float* t_energy     = (const float*)d_in[6];
    const float* t_pos        = (const float*)d_in[7];
    const float* t_time       = (const float*)d_in[8];
    /* d_in[9] = t_pid (unused), d_in[11] = rowsplits (unused) */
    const int*   t_idx        = (const int*)d_in[10];
    int n = in_sizes[0];

    int blocks = (n + 255) / 256;
    k_init  <<<1, 256>>>();
    k_pass1 <<<blocks, 256>>>(pred_beta, t_idx, n);
    k_gather<<<1, 256>>>(pred_beta, pred_ccoords);
    k_point <<<blocks, 256>>>(pred_beta, pred_ccoords, pred_energy, pred_pos,
                              pred_time, pred_id, t_energy, t_pos, t_time, t_idx, n);
    k_rep   <<<blocks, 256>>>(pred_beta, pred_ccoords, n);
    k_final <<<1, 256>>>((float*)d_out, n);
}

// round 3
// speedup vs baseline: 3.1188x; 3.1188x over previous
#include <cuda_runtime.h>

#define K_OBJ 256
#define TILE  256
#define MAIN_BLOCKS 296

// ---- scratch (__device__ globals; no allocations allowed) ----
__device__ unsigned long long g_key[K_OBJ];
__device__ int   g_counts[K_OBJ];
__device__ float g_att[K_OBJ], g_rep[K_OBJ], g_corr[K_OBJ], g_den[K_OBJ], g_num[K_OBJ];
__device__ float g_noise_sum;
__device__ int   g_noise_cnt;
__device__ int   g_ticket;

__device__ __forceinline__ float clip_beta(float b) {
    return fminf(fmaxf(b, 0.0f), 0.99999f); // BETA_CLIP = 1 - 1e-5
}
__device__ __forceinline__ float sqrt_approx(float x) {
    float r; asm("sqrt.approx.f32 %0, %1;" : "=f"(r) : "f"(x)); return r;
}

// ---- K1: zero scratch (re-run every replay) ----
__global__ void k_init() {
    int k = threadIdx.x;
    g_key[k] = 0ull; g_counts[k] = 0;
    g_att[k] = 0.f; g_rep[k] = 0.f; g_corr[k] = 0.f; g_den[k] = 0.f; g_num[k] = 0.f;
    if (k == 0) { g_noise_sum = 0.f; g_noise_cnt = 0; g_ticket = 0; }
}

// ---- K2: counts + argmax-beta per object (lowest-index tie-break), vectorized,
//      shared-memory pre-reduction ----
__global__ void __launch_bounds__(256) k_pass1(const float* __restrict__ pred_beta,
                                               const int*   __restrict__ t_idx, int n) {
    __shared__ unsigned long long skey[K_OBJ];
    __shared__ int scnt[K_OBJ];
    int tid = threadIdx.x;
    skey[tid] = 0ull; scnt[tid] = 0;
    __syncthreads();

    int nv = n >> 2;                       // number of float4 groups
    int j = blockIdx.x * blockDim.x + tid;
    if (j < nv) {
        float4 b4 = ((const float4*)pred_beta)[j];
        int4   t4 = ((const int4*)t_idx)[j];
        int   base = 4 * j;
        float bb[4] = {b4.x, b4.y, b4.z, b4.w};
        int   tt[4] = {t4.x, t4.y, t4.z, t4.w};
        #pragma unroll
        for (int r = 0; r < 4; r++) {
            int t = tt[r];
            if (t >= 0) {
                float b = clip_beta(bb[r]);
                unsigned int i = (unsigned int)(base + r);
                unsigned long long key =
                    ((unsigned long long)__float_as_uint(b) << 32) |
                    (unsigned long long)(~i);
                atomicMax(&skey[t], key);
                atomicAdd(&scnt[t], 1);
            }
        }
    }
    // scalar tail (n % 4) handled by block 0
    if (blockIdx.x == 0 && tid < (n & 3)) {
        int i = (nv << 2) + tid;
        int t = t_idx[i];
        if (t >= 0) {
            float b = clip_beta(pred_beta[i]);
            unsigned long long key =
                ((unsigned long long)__float_as_uint(b) << 32) |
                (unsigned long long)(~(unsigned int)i);
            atomicMax(&skey[t], key);
            atomicAdd(&scnt[t], 1);
        }
    }
    __syncthreads();
    if (skey[tid]) atomicMax(&g_key[tid], skey[tid]);
    if (scnt[tid]) atomicAdd(&g_counts[tid], scnt[tid]);
}

// ---- K3: fused gather + per-point scatter + N*K repulsion ----
__global__ void __launch_bounds__(256) k_main(const float* __restrict__ pred_beta,
                                              const float* __restrict__ cc,
                                              const float* __restrict__ pred_energy,
                                              const float* __restrict__ pred_pos,
                                              const float* __restrict__ pred_time,
                                              const float* __restrict__ t_energy,
                                              const float* __restrict__ t_pos,
                                              const float* __restrict__ t_time,
                                              const int*   __restrict__ t_idx,
                                              int n, int ntiles) {
    __shared__ float4 s_pt[TILE];                 // (ccx, ccy, q, -)
    __shared__ float  s_kx[K_OBJ], s_ky[K_OBJ];
    __shared__ float  s_att[K_OBJ], s_corr[K_OBJ], s_den[K_OBJ], s_num[K_OBJ];
    __shared__ float  s_noise;
    __shared__ int    s_ncnt;
    __shared__ int    s_tile;
    int tid = threadIdx.x;

    // per-object gather: x_k from argmax key (each block redundantly; L2 hits)
    unsigned long long key = g_key[tid];
    unsigned int aidx = ~(unsigned int)(key & 0xFFFFFFFFull);
    if (g_counts[tid] == 0) aidx = 0u;
    float kx = cc[2u * aidx], ky = cc[2u * aidx + 1u];
    s_kx[tid] = kx; s_ky[tid] = ky;
    s_att[tid] = 0.f; s_corr[tid] = 0.f; s_den[tid] = 0.f; s_num[tid] = 0.f;
    if (tid == 0) { s_noise = 0.f; s_ncnt = 0; }
    __syncthreads();

    float rep0 = 0.f, rep1 = 0.f;
    for (;;) {
        if (tid == 0) s_tile = atomicAdd(&g_ticket, 1);
        __syncthreads();
        int tile = s_tile;
        if (tile >= ntiles) break;

        int i = tile * TILE + tid;
        float px = 0.f, py = 0.f, q = 0.f;
        if (i < n) {
            // front-batched, unconditional loads (max MLP)
            float  braw = pred_beta[i];
            float2 c    = ((const float2*)cc)[i];
            int    t    = t_idx[i];
            float  te   = t_energy[i];
            float  pe   = pred_energy[i];
            float2 tp   = ((const float2*)t_pos)[i];
            float2 pp   = ((const float2*)pred_pos)[i];
            float  tt   = t_time[i];
            float  pt   = pred_time[i];

            float b = clip_beta(braw);
            float a = atanhf(b);
            q = a * a + 0.5f;                      // Q_MIN
            px = c.x; py = c.y;

            if (t >= 0) {
                float dx = px - s_kx[t], dy = py - s_ky[t];
                float d2 = fmaf(dx, dx, dy * dy);
                atomicAdd(&s_att[t], q * d2);
                float h = 1.0f - sqrt_approx(d2 + 1e-6f);
                atomicAdd(&s_corr[t], q * fmaxf(h, 0.0f));   // member-hinge correction
                atomicAdd(&s_den[t], b);
                float ew  = (te > 10.0f) ? 1.0f : fmaxf((te - 0.5f) * (1.0f / 9.5f), 0.0f);
                float de  = te - pe;
                float el  = de * de / (te + 1.0f);
                float p0  = tp.x - pp.x, p1 = tp.y - pp.y;
                float pl  = fmaf(p0, p0, p1 * p1) * 0.01f;
                float dt  = tt - pt;
                float pay = fmaf(dt, dt, el + pl) * ew;
                if (braw >= 0.1f) atomicAdd(&s_num[t], pay * b);  // PAYLOAD_BETA_CLIP
            } else {
                atomicAdd(&s_noise, b);
                atomicAdd(&s_ncnt, 1);
            }
        }
        s_pt[tid] = make_float4(px, py, q, 0.f);   // q=0 padding for i>=n
        __syncthreads();

        // hot loop: thread = object, stream 256 points from shared (broadcast)
        #pragma unroll 4
        for (int p = 0; p < TILE; p += 2) {
            float4 P = s_pt[p];
            float dx = P.x - kx, dy = P.y - ky;
            float d2 = fmaf(dx, dx, fmaf(dy, dy, 1e-6f));
            float h  = 1.0f - sqrt_approx(d2);
            rep0 = fmaf(P.z, fmaxf(h, 0.0f), rep0);
            float4 Q = s_pt[p + 1];
            float ex = Q.x - kx, ey = Q.y - ky;
            float e2 = fmaf(ex, ex, fmaf(ey, ey, 1e-6f));
            float g  = 1.0f - sqrt_approx(e2);
            rep1 = fmaf(Q.z, fmaxf(g, 0.0f), rep1);
        }
        __syncthreads();                           // s_pt reuse
    }

    // flush
    atomicAdd(&g_rep[tid],  rep0 + rep1);
    if (s_att[tid]  != 0.f) atomicAdd(&g_att[tid],  s_att[tid]);
    if (s_corr[tid] != 0.f) atomicAdd(&g_corr[tid], s_corr[tid]);
    if (s_den[tid]  != 0.f) atomicAdd(&g_den[tid],  s_den[tid]);
    if (s_num[tid]  != 0.f) atomicAdd(&g_num[tid],  s_num[tid]);
    if (tid == 0 && s_ncnt) {
        atomicAdd(&g_noise_sum, s_noise);
        atomicAdd(&g_noise_cnt, s_ncnt);
    }
}

// ---- K4: final reduce -> scalar ----
__global__ void k_final(const float* __restrict__ pred_beta,
                        float* __restrict__ out, int n) {
    __shared__ double s_sum[K_OBJ];
    __shared__ int    s_nv[K_OBJ];
    int k = threadIdx.x;
    int c = g_counts[k];
    double term = 0.0; int nv = 0;
    if (c > 0) {
        unsigned int aidx = ~(unsigned int)(g_key[k] & 0xFFFFFFFFull);
        float ba = clip_beta(pred_beta[aidx]);
        float a  = atanhf(ba);
        double qa = (double)(a * a + 0.5f);
        term += qa * (double)g_att[k] / (double)c;                 // V_att_k
        int dr = n - c; if (dr < 1) dr = 1;
        term += qa * (double)(g_rep[k] - g_corr[k]) / (double)dr;  // V_rep_k
        term += 1.0 - (double)ba;                                  // L_beta_k
        float den = fmaxf(g_den[k], 1e-6f);
        term += (double)g_num[k] / (double)den;                    // payload_k
        nv = 1;
    }
    s_sum[k] = term; s_nv[k] = nv;
    __syncthreads();
    #pragma unroll
    for (int s = 128; s > 0; s >>= 1) {
        if (k < s) { s_sum[k] += s_sum[k + s]; s_nv[k] += s_nv[k + s]; }
        __syncthreads();
    }
    if (k == 0) {
        double nvd = (s_nv[0] > 0) ? (double)s_nv[0] : 1.0;
        int nc = (g_noise_cnt > 0) ? g_noise_cnt : 1;
        out[0] = (float)(s_sum[0] / nvd + (double)g_noise_sum / (double)nc);
    }
}

extern "C" void kernel_launch(void* const* d_in, const int* in_sizes, int n_in,
                              void* d_out, int out_size) {
    const float* pred_beta    = (const float*)d_in[0];
    const float* pred_ccoords = (const float*)d_in[1];
    const float* pred_energy  = (const float*)d_in[2];
    const float* pred_pos     = (const float*)d_in[3];
    const float* pred_time    = (const float*)d_in[4];
    /* d_in[5] = pred_id: cls term is 1e-8-scale -> negligible, skipped */
    const float* t_energy     = (const float*)d_in[6];
    const float* t_pos        = (const float*)d_in[7];
    const float* t_time       = (const float*)d_in[8];
    /* d_in[9] = t_pid (unused), d_in[11] = rowsplits (unused) */
    const int*   t_idx        = (const int*)d_in[10];
    int n = in_sizes[0];

    int ntiles = (n + TILE - 1) / TILE;
    int p1_blocks = ((n >> 2) + 255) / 256; if (p1_blocks < 1) p1_blocks = 1;
    int mb = MAIN_BLOCKS < ntiles ? MAIN_BLOCKS : ntiles;

    k_init  <<<1, 256>>>();
    k_pass1 <<<p1_blocks, 256>>>(pred_beta, t_idx, n);
    k_main  <<<mb, 256>>>(pred_beta, pred_ccoords, pred_energy, pred_pos, pred_time,
                          t_energy, t_pos, t_time, t_idx, n, ntiles);
    k_final <<<1, 256>>>(pred_beta, (float*)d_out, n);
}

// round 4
// speedup vs baseline: 3.4682x; 1.1120x over previous
#include <cuda_runtime.h>

#define K_OBJ 256
#define TILE  256

// ---- scratch (__device__ globals; zero at module load, reset by the kernel itself) ----
__device__ unsigned long long g_key[K_OBJ];
__device__ int   g_counts[K_OBJ];
__device__ float g_att[K_OBJ], g_rep[K_OBJ], g_corr[K_OBJ], g_den[K_OBJ], g_num[K_OBJ];
__device__ float g_noise_sum;
__device__ int   g_noise_cnt;
__device__ int   g_ticket;
__device__ int   g_bar;

__device__ __forceinline__ float clip_beta(float b) {
    return fminf(fmaxf(b, 0.0f), 0.99999f); // BETA_CLIP = 1 - 1e-5
}
__device__ __forceinline__ float sqrt_approx(float x) {
    float r; asm("sqrt.approx.f32 %0, %1;" : "=f"(r) : "f"(x)); return r;
}

__global__ void __launch_bounds__(256, 2)
k_all(const float* __restrict__ pred_beta,
      const float* __restrict__ cc,
      const float* __restrict__ pred_energy,
      const float* __restrict__ pred_pos,
      const float* __restrict__ pred_time,
      const float* __restrict__ t_energy,
      const float* __restrict__ t_pos,
      const float* __restrict__ t_time,
      const int*   __restrict__ t_idx,
      float* __restrict__ out, int n, int ntiles) {
    __shared__ unsigned long long skey[K_OBJ];
    __shared__ int    scnt[K_OBJ];
    __shared__ float4 s_pt[TILE];                 // (ccx, ccy, q, -)
    __shared__ float  s_kx[K_OBJ], s_ky[K_OBJ];
    __shared__ float  s_att[K_OBJ], s_corr[K_OBJ], s_den[K_OBJ], s_num[K_OBJ];
    __shared__ float  s_noise;
    __shared__ int    s_ncnt, s_tile;

    const int tid  = threadIdx.x;
    const int grid = gridDim.x;

    // ============ Phase A: counts + argmax-beta key per object ============
    skey[tid] = 0ull; scnt[tid] = 0;
    __syncthreads();
    {
        int nv = n >> 2;
        for (int j = blockIdx.x * 256 + tid; j < nv; j += grid * 256) {
            float4 b4 = ((const float4*)pred_beta)[j];
            int4   t4 = ((const int4*)t_idx)[j];
            int base = 4 * j;
            float bb[4] = {b4.x, b4.y, b4.z, b4.w};
            int   tt[4] = {t4.x, t4.y, t4.z, t4.w};
            #pragma unroll
            for (int r = 0; r < 4; r++) {
                int t = tt[r];
                if (t >= 0) {
                    float b = clip_beta(bb[r]);
                    unsigned int i = (unsigned int)(base + r);
                    unsigned long long key =
                        ((unsigned long long)__float_as_uint(b) << 32) |
                        (unsigned long long)(~i);
                    atomicMax(&skey[t], key);
                    atomicAdd(&scnt[t], 1);
                }
            }
        }
        if (blockIdx.x == 0 && tid < (n & 3)) {   // scalar tail
            int i = (nv << 2) + tid;
            int t = t_idx[i];
            if (t >= 0) {
                float b = clip_beta(pred_beta[i]);
                unsigned long long key =
                    ((unsigned long long)__float_as_uint(b) << 32) |
                    (unsigned long long)(~(unsigned int)i);
                atomicMax(&skey[t], key);
                atomicAdd(&scnt[t], 1);
            }
        }
    }
    __syncthreads();
    if (skey[tid]) atomicMax(&g_key[tid], skey[tid]);
    if (scnt[tid]) atomicAdd(&g_counts[tid], scnt[tid]);

    // ---- grid barrier 1 (all blocks wait) ----
    __syncthreads();
    if (tid == 0) {
        __threadfence();
        atomicAdd(&g_bar, 1);
        while (atomicAdd(&g_bar, 0) < grid) {}
    }
    __syncthreads();
    __threadfence();

    // ============ Phase B: gather x_k + point scatter + N*K repulsion ============
    unsigned long long key = __ldcg(&g_key[tid]);
    unsigned int aidx = ~(unsigned int)(key & 0xFFFFFFFFull);
    if (__ldcg(&g_counts[tid]) == 0) aidx = 0u;
    float kx = cc[2u * aidx], ky = cc[2u * aidx + 1u];
    s_kx[tid] = kx; s_ky[tid] = ky;
    s_att[tid] = 0.f; s_corr[tid] = 0.f; s_den[tid] = 0.f; s_num[tid] = 0.f;
    if (tid == 0) { s_noise = 0.f; s_ncnt = 0; }
    __syncthreads();

    float rep0 = 0.f, rep1 = 0.f;
    for (;;) {
        if (tid == 0) s_tile = atomicAdd(&g_ticket, 1);
        __syncthreads();
        int tile = s_tile;
        if (tile >= ntiles) break;

        int i = tile * TILE + tid;
        float px = 0.f, py = 0.f, q = 0.f;
        if (i < n) {
            float  braw = pred_beta[i];            // front-batched loads
            float2 c    = ((const float2*)cc)[i];
            int    t    = t_idx[i];
            float  te   = t_energy[i];
            float  pe   = pred_energy[i];
            float2 tp   = ((const float2*)t_pos)[i];
            float2 pp   = ((const float2*)pred_pos)[i];
            float  tt   = t_time[i];
            float  pt   = pred_time[i];

            float b = clip_beta(braw);
            float a = atanhf(b);
            q = a * a + 0.5f;                      // Q_MIN
            px = c.x; py = c.y;

            if (t >= 0) {
                float dx = px - s_kx[t], dy = py - s_ky[t];
                float d2 = fmaf(dx, dx, dy * dy);
                atomicAdd(&s_att[t], q * d2);
                float h = 1.0f - sqrt_approx(d2 + 1e-6f);
                atomicAdd(&s_corr[t], q * fmaxf(h, 0.0f));
                atomicAdd(&s_den[t], b);
                float ew  = (te > 10.0f) ? 1.0f : fmaxf((te - 0.5f) * (1.0f / 9.5f), 0.0f);
                float de  = te - pe;
                float el  = de * de / (te + 1.0f);
                float p0  = tp.x - pp.x, p1 = tp.y - pp.y;
                float pl  = fmaf(p0, p0, p1 * p1) * 0.01f;
                float dt  = tt - pt;
                float pay = fmaf(dt, dt, el + pl) * ew;
                if (braw >= 0.1f) atomicAdd(&s_num[t], pay * b);  // PAYLOAD_BETA_CLIP
            } else {
                atomicAdd(&s_noise, b);
                atomicAdd(&s_ncnt, 1);
            }
        }
        s_pt[tid] = make_float4(px, py, q, 0.f);
        __syncthreads();

        #pragma unroll 4
        for (int p = 0; p < TILE; p += 2) {
            float4 P = s_pt[p];
            float dx = P.x - kx, dy = P.y - ky;
            float d2 = fmaf(dx, dx, fmaf(dy, dy, 1e-6f));
            float h  = 1.0f - sqrt_approx(d2);
            rep0 = fmaf(P.z, fmaxf(h, 0.0f), rep0);
            float4 Q = s_pt[p + 1];
            float ex = Q.x - kx, ey = Q.y - ky;
            float e2 = fmaf(ex, ex, fmaf(ey, ey, 1e-6f));
            float g  = 1.0f - sqrt_approx(e2);
            rep1 = fmaf(Q.z, fmaxf(g, 0.0f), rep1);
        }
        __syncthreads();
    }

    atomicAdd(&g_rep[tid],  rep0 + rep1);
    if (s_att[tid]  != 0.f) atomicAdd(&g_att[tid],  s_att[tid]);
    if (s_corr[tid] != 0.f) atomicAdd(&g_corr[tid], s_corr[tid]);
    if (s_den[tid]  != 0.f) atomicAdd(&g_den[tid],  s_den[tid]);
    if (s_num[tid]  != 0.f) atomicAdd(&g_num[tid],  s_num[tid]);
    if (tid == 0 && s_ncnt) {
        atomicAdd(&g_noise_sum, s_noise);
        atomicAdd(&g_noise_cnt, s_ncnt);
    }

    // ---- grid barrier 2: arrive-only for blocks != 0 (they exit -> no reset hazard) ----
    __syncthreads();
    if (tid == 0) { __threadfence(); atomicAdd(&g_bar, 1); }
    if (blockIdx.x != 0) return;
    if (tid == 0) {
        while (atomicAdd(&g_bar, 0) < 2 * grid) {}
        __threadfence();
    }
    __syncthreads();

    // ============ Phase C (block 0): final fp32 reduce + consume-and-reset ============
    {
        int   c    = __ldcg(&g_counts[tid]);
        float attv = __ldcg(&g_att[tid]);
        float repv = __ldcg(&g_rep[tid]);
        float corv = __ldcg(&g_corr[tid]);
        float denv = __ldcg(&g_den[tid]);
        float numv = __ldcg(&g_num[tid]);
        unsigned long long kk = __ldcg(&g_key[tid]);

        float term = 0.f; int nv = 0;
        if (c > 0) {
            unsigned int ai = ~(unsigned int)(kk & 0xFFFFFFFFull);
            float ba = clip_beta(pred_beta[ai]);
            float a  = atanhf(ba);
            float qa = a * a + 0.5f;
            int dr = n - c; if (dr < 1) dr = 1;
            term = qa * attv / (float)c
                 + qa * (repv - corv) / (float)dr
                 + (1.0f - ba)
                 + numv / fmaxf(denv, 1e-6f);
            nv = 1;
        }
        // reset scratch for next replay (deterministic consume-and-reset)
        g_key[tid] = 0ull; g_counts[tid] = 0;
        g_att[tid] = 0.f; g_rep[tid] = 0.f; g_corr[tid] = 0.f;
        g_den[tid] = 0.f; g_num[tid] = 0.f;

        s_att[tid] = term;                 // reuse shared for reduction
        scnt[tid]  = nv;
        __syncthreads();
        #pragma unroll
        for (int s = 128; s > 0; s >>= 1) {
            if (tid < s) { s_att[tid] += s_att[tid + s]; scnt[tid] += scnt[tid + s]; }
            __syncthreads();
        }
        if (tid == 0) {
            float nvd = (scnt[0] > 0) ? (float)scnt[0] : 1.0f;
            int   nc  = g_noise_cnt; if (nc < 1) nc = 1;
            out[0] = s_att[0] / nvd + g_noise_sum / (float)nc;
            g_noise_sum = 0.f; g_noise_cnt = 0; g_ticket = 0; g_bar = 0;
        }
    }
}

extern "C" void kernel_launch(void* const* d_in, const int* in_sizes, int n_in,
                              void* d_out, int out_size) {
    const float* pred_beta    = (const float*)d_in[0];
    const float* pred_ccoords = (const float*)d_in[1];
    const float* pred_energy  = (const float*)d_in[2];
    const float* pred_pos     = (const float*)d_in[3];
    const float* pred_time    = (const float*)d_in[4];
    /* d_in[5] = pred_id: cls term is 1e-8-scale -> negligible */
    const float* t_energy     = (const float*)d_in[6];
    const float* t_pos        = (const float*)d_in[7];
    const float* t_time       = (const float*)d_in[8];
    /* d_in[9] = t_pid, d_in[11] = rowsplits: unused */
    const int*   t_idx        = (const int*)d_in[10];
    int n = in_sizes[0];

    int ntiles = (n + TILE - 1) / TILE;

    // all blocks must be co-resident for the software grid barrier
    int sm = 0, per_sm = 0;
    cudaDeviceGetAttribute(&sm, cudaDevAttrMultiProcessorCount, 0);
    cudaOccupancyMaxActiveBlocksPerMultiprocessor(&per_sm, k_all, 256, 0);
    if (per_sm > 2) per_sm = 2;
    if (per_sm < 1) per_sm = 1;
    int blocks = sm * per_sm;
    if (blocks > ntiles) blocks = ntiles;
    if (blocks < 1) blocks = 1;

    k_all<<<blocks, 256>>>(pred_beta, pred_ccoords, pred_energy, pred_pos, pred_time,
                           t_energy, t_pos, t_time, t_idx, (float*)d_out, n, ntiles);
}